// round 9
// baseline (speedup 1.0000x reference)
#include <cuda_runtime.h>
#include <cuda_bf16.h>
#include <cstdint>

// Per-batch 21x21 cross-correlation, reflect padding 10.
// input: (16,3,768,768) f32   kernel: (16,21,21) f32   out: (16,3,768,768) f32
// FFMA2 (fma.rn.f32x2), lanes = two adjacent OUTPUT ROWS.
// R9: R7 config + SW64 XOR bank-swizzle on the input tile to kill the 2-way
//     LDS.128 bank conflict (lane stride 32B -> lanes 0&4 shared banks).

#define BB 16
#define CC 3
#define HH 768
#define WW 768
#define KK 21
#define PP 10

#define TH 64            // output rows per CTA (4 per thread: 16 ty groups)
#define TW 128           // output cols per CTA (8 per thread: 16 tx groups)
#define IH (TH + KK - 1) // 84 input rows in tile
#define IW (TW + KK - 1) // 148 input cols needed
#define SW 152           // smem tile row stride (floats), 16B aligned (608B)
#define QJ 24            // quads per table row (21 real + pad)

#define TILE_FLOATS (IH * SW)                 // 12768
#define QUAD_COUNT  (24 * QJ)                 // 576 quads (16B each)
#define SMEM_BYTES  (TILE_FLOATS * 4 + QUAD_COUNT * 16)   // 51072 + 9216 = 60288

// XOR bank swizzle: rotate bits[4:5] by bits[7:8]; preserves 16B alignment.
__device__ __forceinline__ uint32_t swz(uint32_t byte_off) {
    return byte_off ^ ((byte_off >> 3) & 0x30u);
}

__device__ __forceinline__ int reflect_idx(int t) {
    if (t < 0) return -t;
    if (t >= HH) return 2 * HH - 2 - t;
    return t;
}

// d.lo += a.lo*b.lo ; d.hi += a.hi*b.hi   (one SASS FFMA2)
__device__ __forceinline__ void ffma2(double& d, double a, double b) {
    asm("fma.rn.f32x2 %0, %1, %2, %0;"
        : "+d"(d) : "l"(__double_as_longlong(a)), "l"(__double_as_longlong(b)));
}

// broadcast float into both lanes of a 64b pair
__device__ __forceinline__ double bcast(float x) {
    double r;
    asm("mov.b64 %0, {%1, %1};" : "=d"(r) : "f"(x));
    return r;
}

__device__ __forceinline__ void unpack2(float& lo, float& hi, double p) {
    asm("mov.b64 {%0, %1}, %2;" : "=f"(lo), "=f"(hi) : "d"(p));
}

__device__ __forceinline__ void cp_async4(uint32_t dst_smem, const float* src) {
    asm volatile("cp.async.ca.shared.global [%0], [%1], 4;"
                 :: "r"(dst_smem), "l"(src));
}

__global__ __launch_bounds__(256, 3)
void blur_kernel(const float* __restrict__ in,
                 const float* __restrict__ ker,
                 float* __restrict__ out)
{
    extern __shared__ float smem[];
    float* tile = smem;                                    // IH x SW floats (swizzled)
    float* qtab = smem + TILE_FLOATS;                      // 24 x QJ quads (float4)

    const int tid  = threadIdx.x;
    const int lane = tid & 31;
    const int wrp  = tid >> 5;             // 0..7
    const int bx = blockIdx.x;             // 0..5   W tiles
    const int by = blockIdx.y;             // 0..11  H tiles
    const int bz = blockIdx.z;             // 0..47  b*3+c
    const int b  = bz / CC;

    const uint32_t tile_base = (uint32_t)__cvta_generic_to_shared(tile);
    const uint32_t kern_base = (uint32_t)__cvta_generic_to_shared(qtab);

    // ---- input halo tile via cp.async (swizzled dst): warp-per-row ----
    {
        const int gh0 = by * TH - PP;
        const int gw0 = bx * TW - PP;
        const float* img = in + (long)bz * (HH * WW);
        #pragma unroll 1
        for (int r = wrp; r < IH; r += 8) {
            const float* src = img + (long)reflect_idx(gh0 + r) * WW;
            const uint32_t roff = (uint32_t)(r * SW * 4);
            #pragma unroll
            for (int c5 = 0; c5 < 5; ++c5) {
                int cc = c5 * 32 + lane;             // 0..159
                if (cc < IW) {
                    cp_async4(tile_base + swz(roff + cc * 4),
                              src + reflect_idx(gw0 + cc));
                }
            }
        }
    }

    // ---- build weight QUAD table while cp.async is in flight ----
    // quad[t][j] = (w[t][j], w[t-1][j], w[t-2][j], w[t-3][j]), zeros outside [0,20]
    {
        const float* kb = ker + b * (KK * KK);
        float4* q4 = (float4*)qtab;
        #pragma unroll 1
        for (int idx = tid; idx < QUAD_COUNT; idx += 256) {
            int t = idx / QJ;
            int j = idx - t * QJ;
            float v0 = 0.f, v1 = 0.f, v2 = 0.f, v3 = 0.f;
            if (j < KK) {
                if (t     <= 20)           v0 = kb[t * KK + j];
                if (t >= 1 && t - 1 <= 20) v1 = kb[(t - 1) * KK + j];
                if (t >= 2 && t - 2 <= 20) v2 = kb[(t - 2) * KK + j];
                if (t >= 3 && t - 3 <= 20) v3 = kb[(t - 3) * KK + j];
            }
            q4[idx] = make_float4(v0, v1, v2, v3);
        }
    }

    asm volatile("cp.async.commit_group;" ::: "memory");
    asm volatile("cp.async.wait_group 0;" ::: "memory");
    __syncthreads();

    const int tx = tid & 15;     // 0..15 -> 8-wide column group
    const int ty = tid >> 4;     // 0..15 -> 4-row group
    const int wc = tx * 8;       // local col of first output
    const int rb = ty * 4;       // first output row of this thread

    // accumulators: pcA lanes = (row rb, rb+1), pcB lanes = (row rb+2, rb+3)
    double pcA[8], pcB[8];
    #pragma unroll
    for (int c = 0; c < 8; ++c) { pcA[c] = 0.0; pcB[c] = 0.0; }

    double xb[28];   // broadcast pairs of the 28-float window
    const uint32_t win_base = tile_base + (uint32_t)((rb * SW + wc) * 4);

    #define LOADROW(r) do {                                                   \
        const uint32_t ro_ = (uint32_t)((rb + (r)) * SW + wc) * 4 ;           \
        _Pragma("unroll")                                                     \
        for (int v = 0; v < 7; ++v) {                                         \
            float4 q_;                                                        \
            const uint32_t a_ = tile_base + swz(ro_ + v * 16);                \
            asm volatile("ld.shared.v4.f32 {%0, %1, %2, %3}, [%4];"           \
                         : "=f"(q_.x), "=f"(q_.y), "=f"(q_.z), "=f"(q_.w)     \
                         : "r"(a_));                                          \
            xb[4*v+0] = bcast(q_.x); xb[4*v+1] = bcast(q_.y);                 \
            xb[4*v+2] = bcast(q_.z); xb[4*v+3] = bcast(q_.w);                 \
        }                                                                     \
    } while (0)

    // both acc sets, one LDS.128 per j: lo pair -> pcA, hi pair -> pcB
    #define ACC2Q(r) do {                                                     \
        const uint32_t qa_ = kern_base + (uint32_t)((r) * (QJ * 16));         \
        _Pragma("unroll")                                                     \
        for (int j = 0; j < KK; ++j) {                                        \
            unsigned long long la_, lb_;                                      \
            asm volatile("ld.shared.v2.u64 {%0, %1}, [%2];"                   \
                         : "=l"(la_), "=l"(lb_) : "r"(qa_ + j * 16));         \
            const double wA_ = __longlong_as_double(la_);                     \
            const double wB_ = __longlong_as_double(lb_);                     \
            _Pragma("unroll")                                                 \
            for (int c = 0; c < 8; ++c) {                                     \
                ffma2(pcA[c], xb[j + c], wA_);                                \
                ffma2(pcB[c], xb[j + c], wB_);                                \
            }                                                                 \
        }                                                                     \
    } while (0)

    // single acc set; off = 0 -> lo pair (pcA), off = 8 -> hi pair (pcB)
    #define ACC1P(PC, r, off) do {                                            \
        const uint32_t qa_ = kern_base + (uint32_t)((r) * (QJ * 16) + (off)); \
        _Pragma("unroll")                                                     \
        for (int j = 0; j < KK; ++j) {                                        \
            unsigned long long l_;                                            \
            asm volatile("ld.shared.b64 %0, [%1];"                            \
                         : "=l"(l_) : "r"(qa_ + j * 16));                     \
            const double w_ = __longlong_as_double(l_);                       \
            _Pragma("unroll")                                                 \
            for (int c = 0; c < 8; ++c) ffma2(PC[c], xb[j + c], w_);          \
        }                                                                     \
    } while (0)

    // r = 0,1: only pcA (pairs (w0,0), (w1,w0))
    LOADROW(0); ACC1P(pcA, 0, 0);
    LOADROW(1); ACC1P(pcA, 1, 0);

    // r = 2..21: pcA with (w[r],w[r-1]), pcB with (w[r-2],w[r-3])
    #pragma unroll 1
    for (int r = 2; r <= 21; ++r) {
        LOADROW(r);
        ACC2Q(r);
    }

    // r = 22,23: only pcB (hi pairs (w20,w19), (0,w20))
    LOADROW(22); ACC1P(pcB, 22, 8);
    LOADROW(23); ACC1P(pcB, 23, 8);

    (void)win_base;

    // ---- unpack lanes, write 4 x 8 outputs ----
    const int oh = by * TH + rb;
    const int ow = bx * TW + wc;
    float* op = out + (long)bz * (HH * WW) + (long)oh * WW + ow;

    float r0[8], r1[8], r2[8], r3[8];
    #pragma unroll
    for (int c = 0; c < 8; ++c) {
        unpack2(r0[c], r1[c], pcA[c]);
        unpack2(r2[c], r3[c], pcB[c]);
    }
    #pragma unroll
    for (int v = 0; v < 2; ++v) {
        *reinterpret_cast<float4*>(op + 0*WW + 4*v) = make_float4(r0[4*v], r0[4*v+1], r0[4*v+2], r0[4*v+3]);
        *reinterpret_cast<float4*>(op + 1*WW + 4*v) = make_float4(r1[4*v], r1[4*v+1], r1[4*v+2], r1[4*v+3]);
        *reinterpret_cast<float4*>(op + 2*WW + 4*v) = make_float4(r2[4*v], r2[4*v+1], r2[4*v+2], r2[4*v+3]);
        *reinterpret_cast<float4*>(op + 3*WW + 4*v) = make_float4(r3[4*v], r3[4*v+1], r3[4*v+2], r3[4*v+3]);
    }

    #undef LOADROW
    #undef ACC2Q
    #undef ACC1P
}

extern "C" void kernel_launch(void* const* d_in, const int* in_sizes, int n_in,
                              void* d_out, int out_size)
{
    const float* in  = (const float*)d_in[0];   // (16,3,768,768)
    const float* ker = (const float*)d_in[1];   // (16,21,21)
    float* out = (float*)d_out;

    cudaFuncSetAttribute(blur_kernel,
                         cudaFuncAttributeMaxDynamicSharedMemorySize, SMEM_BYTES);

    dim3 grid(WW / TW, HH / TH, BB * CC);       // (6, 12, 48)
    blur_kernel<<<grid, 256, SMEM_BYTES>>>(in, ker, out);
}

// round 11
// speedup vs baseline: 1.0196x; 1.0196x over previous
#include <cuda_runtime.h>
#include <cuda_bf16.h>
#include <cstdint>

// Per-batch 21x21 cross-correlation, reflect padding 10.
// input: (16,3,768,768) f32   kernel: (16,21,21) f32   out: (16,3,768,768) f32
// FFMA2 (fma.rn.f32x2), lanes = two adjacent OUTPUT ROWS.
// R10: R7 structure + explicit ping-pong prefetch of the window LDS.128s
//      (row r+2 loads issued under row r's FFMA2s), 2 CTAs/SM, 128-reg budget.

#define BB 16
#define CC 3
#define HH 768
#define WW 768
#define KK 21
#define PP 10

#define TH 64            // output rows per CTA (4 per thread: 16 ty groups)
#define TW 128           // output cols per CTA (8 per thread: 16 tx groups)
#define IH (TH + KK - 1) // 84 input rows in tile
#define IW (TW + KK - 1) // 148 input cols needed
#define SW 152           // smem tile row stride (floats), 16B aligned
#define QJ 24            // quads per table row (21 real + pad)

#define TILE_FLOATS (IH * SW)                 // 12768
#define QUAD_COUNT  (24 * QJ)                 // 576 quads (16B each)
#define SMEM_BYTES  (TILE_FLOATS * 4 + QUAD_COUNT * 16)   // 60288

__device__ __forceinline__ int reflect_idx(int t) {
    if (t < 0) return -t;
    if (t >= HH) return 2 * HH - 2 - t;
    return t;
}

// d.lo += a.lo*b.lo ; d.hi += a.hi*b.hi   (one SASS FFMA2)
__device__ __forceinline__ void ffma2(double& d, double a, double b) {
    asm("fma.rn.f32x2 %0, %1, %2, %0;"
        : "+d"(d) : "l"(__double_as_longlong(a)), "l"(__double_as_longlong(b)));
}

// broadcast float into both lanes of a 64b pair
__device__ __forceinline__ double bcast(float x) {
    double r;
    asm("mov.b64 %0, {%1, %1};" : "=d"(r) : "f"(x));
    return r;
}

__device__ __forceinline__ void unpack2(float& lo, float& hi, double p) {
    asm("mov.b64 {%0, %1}, %2;" : "=f"(lo), "=f"(hi) : "d"(p));
}

__device__ __forceinline__ void cp_async4(uint32_t dst_smem, const float* src) {
    asm volatile("cp.async.ca.shared.global [%0], [%1], 4;"
                 :: "r"(dst_smem), "l"(src));
}

__global__ __launch_bounds__(256, 2)
void blur_kernel(const float* __restrict__ in,
                 const float* __restrict__ ker,
                 float* __restrict__ out)
{
    extern __shared__ float smem[];
    float* tile = smem;                                    // IH x SW floats
    float* qtab = smem + TILE_FLOATS;                      // 24 x QJ quads (float4)

    const int tid  = threadIdx.x;
    const int lane = tid & 31;
    const int wrp  = tid >> 5;             // 0..7
    const int bx = blockIdx.x;             // 0..5   W tiles
    const int by = blockIdx.y;             // 0..11  H tiles
    const int bz = blockIdx.z;             // 0..47  b*3+c
    const int b  = bz / CC;

    const uint32_t tile_base = (uint32_t)__cvta_generic_to_shared(tile);
    const uint32_t kern_base = (uint32_t)__cvta_generic_to_shared(qtab);

    // ---- input halo tile via cp.async: warp-per-row, lane-per-col ----
    {
        const int gh0 = by * TH - PP;
        const int gw0 = bx * TW - PP;
        const float* img = in + (long)bz * (HH * WW);
        #pragma unroll 1
        for (int r = wrp; r < IH; r += 8) {
            const float* src = img + (long)reflect_idx(gh0 + r) * WW;
            uint32_t dst = tile_base + (uint32_t)(r * SW * 4);
            #pragma unroll
            for (int c5 = 0; c5 < 5; ++c5) {
                int cc = c5 * 32 + lane;             // 0..159
                if (cc < IW) {
                    cp_async4(dst + cc * 4, src + reflect_idx(gw0 + cc));
                }
            }
        }
    }

    // ---- build weight QUAD table while cp.async is in flight ----
    // quad[t][j] = (w[t][j], w[t-1][j], w[t-2][j], w[t-3][j]), zeros outside [0,20]
    {
        const float* kb = ker + b * (KK * KK);
        float4* q4 = (float4*)qtab;
        #pragma unroll 1
        for (int idx = tid; idx < QUAD_COUNT; idx += 256) {
            int t = idx / QJ;
            int j = idx - t * QJ;
            float v0 = 0.f, v1 = 0.f, v2 = 0.f, v3 = 0.f;
            if (j < KK) {
                if (t     <= 20)           v0 = kb[t * KK + j];
                if (t >= 1 && t - 1 <= 20) v1 = kb[(t - 1) * KK + j];
                if (t >= 2 && t - 2 <= 20) v2 = kb[(t - 2) * KK + j];
                if (t >= 3 && t - 3 <= 20) v3 = kb[(t - 3) * KK + j];
            }
            q4[idx] = make_float4(v0, v1, v2, v3);
        }
    }

    asm volatile("cp.async.commit_group;" ::: "memory");
    asm volatile("cp.async.wait_group 0;" ::: "memory");
    __syncthreads();

    const int tx = tid & 15;     // 0..15 -> 8-wide column group
    const int ty = tid >> 4;     // 0..15 -> 4-row group
    const int wc = tx * 8;       // local col of first output
    const int rb = ty * 4;       // first output row of this thread

    // accumulators: pcA lanes = (row rb, rb+1), pcB lanes = (row rb+2, rb+3)
    double pcA[8], pcB[8];
    #pragma unroll
    for (int c = 0; c < 8; ++c) { pcA[c] = 0.0; pcB[c] = 0.0; }

    double xb[28];        // broadcast pairs of the 28-float window (current row)
    float4 qa[7], qb[7];  // ping-pong raw window buffers

    // raw 7 x LDS.128 of window row r into Q
    #define LOADRAW(Q, r) do {                                                \
        const float* rp_ = &tile[(rb + (r)) * SW + wc];                       \
        _Pragma("unroll")                                                     \
        for (int v = 0; v < 7; ++v)                                           \
            Q[v] = *reinterpret_cast<const float4*>(rp_ + 4 * v);             \
    } while (0)

    // pack raw buffer into broadcast pairs
    #define PACK(Q) do {                                                      \
        _Pragma("unroll")                                                     \
        for (int v = 0; v < 7; ++v) {                                         \
            xb[4*v+0] = bcast(Q[v].x); xb[4*v+1] = bcast(Q[v].y);             \
            xb[4*v+2] = bcast(Q[v].z); xb[4*v+3] = bcast(Q[v].w);             \
        }                                                                     \
    } while (0)

    // both acc sets, one LDS.128 per j: lo pair -> pcA, hi pair -> pcB
    #define ACC2Q(r) do {                                                     \
        const uint32_t qa_ = kern_base + (uint32_t)((r) * (QJ * 16));         \
        _Pragma("unroll")                                                     \
        for (int j = 0; j < KK; ++j) {                                        \
            unsigned long long la_, lb_;                                      \
            asm volatile("ld.shared.v2.u64 {%0, %1}, [%2];"                   \
                         : "=l"(la_), "=l"(lb_) : "r"(qa_ + j * 16));         \
            const double wA_ = __longlong_as_double(la_);                     \
            const double wB_ = __longlong_as_double(lb_);                     \
            _Pragma("unroll")                                                 \
            for (int c = 0; c < 8; ++c) {                                     \
                ffma2(pcA[c], xb[j + c], wA_);                                \
                ffma2(pcB[c], xb[j + c], wB_);                                \
            }                                                                 \
        }                                                                     \
    } while (0)

    // single acc set; off = 0 -> lo pair (pcA), off = 8 -> hi pair (pcB)
    #define ACC1P(PC, r, off) do {                                            \
        const uint32_t qa_ = kern_base + (uint32_t)((r) * (QJ * 16) + (off)); \
        _Pragma("unroll")                                                     \
        for (int j = 0; j < KK; ++j) {                                        \
            unsigned long long l_;                                            \
            asm volatile("ld.shared.b64 %0, [%1];"                            \
                         : "=l"(l_) : "r"(qa_ + j * 16));                     \
            const double w_ = __longlong_as_double(l_);                       \
            _Pragma("unroll")                                                 \
            for (int c = 0; c < 8; ++c) ffma2(PC[c], xb[j + c], w_);          \
        }                                                                     \
    } while (0)

    // prologue: rows 0 and 1 (pcA only), prefetch rows 2 and 3
    LOADRAW(qa, 0);
    LOADRAW(qb, 1);
    PACK(qa); LOADRAW(qa, 2); ACC1P(pcA, 0, 0);
    PACK(qb); LOADRAW(qb, 3); ACC1P(pcA, 1, 0);

    // steady state: rows 2..21, prefetch up to row 23
    #pragma unroll 1
    for (int r = 2; r <= 20; r += 2) {
        PACK(qa); LOADRAW(qa, r + 2); ACC2Q(r);
        PACK(qb); LOADRAW(qb, r + 3); ACC2Q(r + 1);
    }

    // epilogue: rows 22, 23 (pcB only) — qa holds row 22, qb holds row 23
    PACK(qa); ACC1P(pcB, 22, 8);
    PACK(qb); ACC1P(pcB, 23, 8);

    // ---- unpack lanes, write 4 x 8 outputs ----
    const int oh = by * TH + rb;
    const int ow = bx * TW + wc;
    float* op = out + (long)bz * (HH * WW) + (long)oh * WW + ow;

    float r0[8], r1[8], r2[8], r3[8];
    #pragma unroll
    for (int c = 0; c < 8; ++c) {
        unpack2(r0[c], r1[c], pcA[c]);
        unpack2(r2[c], r3[c], pcB[c]);
    }
    #pragma unroll
    for (int v = 0; v < 2; ++v) {
        *reinterpret_cast<float4*>(op + 0*WW + 4*v) = make_float4(r0[4*v], r0[4*v+1], r0[4*v+2], r0[4*v+3]);
        *reinterpret_cast<float4*>(op + 1*WW + 4*v) = make_float4(r1[4*v], r1[4*v+1], r1[4*v+2], r1[4*v+3]);
        *reinterpret_cast<float4*>(op + 2*WW + 4*v) = make_float4(r2[4*v], r2[4*v+1], r2[4*v+2], r2[4*v+3]);
        *reinterpret_cast<float4*>(op + 3*WW + 4*v) = make_float4(r3[4*v], r3[4*v+1], r3[4*v+2], r3[4*v+3]);
    }

    #undef LOADRAW
    #undef PACK
    #undef ACC2Q
    #undef ACC1P
}

extern "C" void kernel_launch(void* const* d_in, const int* in_sizes, int n_in,
                              void* d_out, int out_size)
{
    const float* in  = (const float*)d_in[0];   // (16,3,768,768)
    const float* ker = (const float*)d_in[1];   // (16,21,21)
    float* out = (float*)d_out;

    cudaFuncSetAttribute(blur_kernel,
                         cudaFuncAttributeMaxDynamicSharedMemorySize, SMEM_BYTES);

    dim3 grid(WW / TW, HH / TH, BB * CC);       // (6, 12, 48)
    blur_kernel<<<grid, 256, SMEM_BYTES>>>(in, ker, out);
}